// round 13
// baseline (speedup 1.0000x reference)
#include <cuda_runtime.h>
#include <cuda_fp16.h>
#include <cstdint>

#define BB 16
#define NN 1024
#define HH 768
#define NEG_INF_F (-9000000000000000.0f)
#define SLOPE_F 0.2f

// ---- static device scratch (no allocations allowed) ----
__device__ __align__(16) __half g_xT[(size_t)BB * HH * NN];     // xT fp16 [b][h][k] 25 MB
__device__ uint32_t g_mask[(size_t)BB * NN * 32];               // 2 MB
__device__ __align__(16) float g_u1[HH], g_u2[HH];
__device__ float g_v1[BB * NN], g_v2[BB * NN];
__device__ float g_s1[BB * NN], g_s2[BB * NN];

__device__ __forceinline__ uint32_t smem_u32(const void* p) {
    uint32_t a;
    asm("{ .reg .u64 t; cvta.to.shared.u64 t, %1; cvt.u32.u64 %0, t; }" : "=r"(a) : "l"(p));
    return a;
}
__device__ __forceinline__ void cp_async16(uint32_t dst, const void* src) {
    asm volatile("cp.async.cg.shared.global [%0], [%1], 16;" :: "r"(dst), "l"(src) : "memory");
}
__device__ __forceinline__ void ldmx4(uint32_t& r0, uint32_t& r1, uint32_t& r2, uint32_t& r3, uint32_t a) {
    asm volatile("ldmatrix.sync.aligned.m8n8.x4.shared.b16 {%0,%1,%2,%3}, [%4];"
                 : "=r"(r0), "=r"(r1), "=r"(r2), "=r"(r3) : "r"(a));
}
__device__ __forceinline__ void mma16816(float* d, const uint32_t* a, const uint32_t* b) {
    asm volatile("mma.sync.aligned.m16n8k16.row.col.f32.f16.f16.f32 "
                 "{%0,%1,%2,%3}, {%4,%5,%6,%7}, {%8,%9}, {%0,%1,%2,%3};"
                 : "+f"(d[0]), "+f"(d[1]), "+f"(d[2]), "+f"(d[3])
                 : "r"(a[0]), "r"(a[1]), "r"(a[2]), "r"(a[3]), "r"(b[0]), "r"(b[1]));
}

// ---------------------------------------------------------------------------
// prep_mask: adj fp32 -> validity bitmask only
// ---------------------------------------------------------------------------
__global__ void prep_mask_kernel(const float* __restrict__ adj) {
    __shared__ unsigned char s_nib[256];
    const int row = blockIdx.x;
    const int t = threadIdx.x;
    const float4 v = ((const float4*)(adj + (size_t)row * NN))[t];
    unsigned nib = (v.x > 1e-6f ? 1u : 0u) | (v.y > 1e-6f ? 2u : 0u) |
                   (v.z > 1e-6f ? 4u : 0u) | (v.w > 1e-6f ? 8u : 0u);
    s_nib[t] = (unsigned char)nib;
    __syncthreads();
    if (t < 32) {
        uint32_t w = 0;
#pragma unroll
        for (int i = 0; i < 8; ++i) w |= ((uint32_t)s_nib[t * 8 + i]) << (4 * i);
        g_mask[(size_t)row * 32 + t] = w;
    }
}

// ---------------------------------------------------------------------------
// prep_x: transpose to fp16 xT[b][h][k], packed half2 stores
// ---------------------------------------------------------------------------
__global__ void prep_x_kernel(const float* __restrict__ x) {
    __shared__ float tile[64][33];
    const int b = blockIdx.z;
    const int k0 = blockIdx.y * 64;
    const int h0 = blockIdx.x * 32;
    const int t = threadIdx.x;
    const int wid = t >> 5, lane = t & 31;

#pragma unroll
    for (int i = 0; i < 8; ++i) {
        int r = wid + i * 8;
        tile[r][lane] = x[((size_t)(b * NN + k0 + r)) * HH + h0 + lane];
    }
    __syncthreads();

    uint32_t* xo = (uint32_t*)g_xT;
#pragma unroll
    for (int i = 0; i < 4; ++i) {
        const int h = h0 + wid + i * 8;
        const __half2 p = __floats2half2_rn(tile[2 * lane][wid + i * 8],
                                            tile[2 * lane + 1][wid + i * 8]);
        const size_t base = ((size_t)(b * HH + h)) * (NN / 2) + (k0 >> 1);
        xo[base + lane] = *(const uint32_t*)&p;
    }
}

// ---------------------------------------------------------------------------
// u1 = W @ a[:H], u2 = W @ a[H:]  — one warp per output element
// ---------------------------------------------------------------------------
__global__ void compute_u_kernel(const float* __restrict__ W, const float* __restrict__ a) {
    const int g = blockIdx.x * 8 + (threadIdx.x >> 5);
    const int lane = threadIdx.x & 31;
    const float* wr = W + (size_t)g * HH;
    float u1 = 0.f, u2 = 0.f;
#pragma unroll
    for (int f = lane; f < HH; f += 32) {
        const float w = wr[f];
        u1 += w * a[f];
        u2 += w * a[HH + f];
    }
#pragma unroll
    for (int o = 16; o > 0; o >>= 1) {
        u1 += __shfl_down_sync(0xffffffffu, u1, o);
        u2 += __shfl_down_sync(0xffffffffu, u2, o);
    }
    if (lane == 0) { g_u1[g] = u1; g_u2[g] = u2; }
}

// ---------------------------------------------------------------------------
// v1[b,j] = x[b,j,:].u1 ; v2 = x.u2   (one warp per row, exact fp32)
// ---------------------------------------------------------------------------
__global__ void compute_v_kernel(const float* __restrict__ x) {
    const int row = blockIdx.x * 8 + (threadIdx.x >> 5);
    const int lane = threadIdx.x & 31;
    const float4* r = (const float4*)(x + (size_t)row * HH);
    const float4* u1 = (const float4*)g_u1;
    const float4* u2 = (const float4*)g_u2;
    float d1 = 0.f, d2 = 0.f;
#pragma unroll
    for (int k = lane; k < HH / 4; k += 32) {
        float4 v = r[k], w1 = u1[k], w2 = u2[k];
        d1 += v.x * w1.x + v.y * w1.y + v.z * w1.z + v.w * w1.w;
        d2 += v.x * w2.x + v.y * w2.y + v.z * w2.z + v.w * w2.w;
    }
#pragma unroll
    for (int o = 16; o > 0; o >>= 1) {
        d1 += __shfl_down_sync(0xffffffffu, d1, o);
        d2 += __shfl_down_sync(0xffffffffu, d2, o);
    }
    if (lane == 0) { g_v1[row] = d1; g_v2[row] = d2; }
}

// ---------------------------------------------------------------------------
// s1[b,i] = sum_{j in mask(i)} v1[b,j]   (exact fp32)
// ---------------------------------------------------------------------------
__global__ void compute_s_kernel() {
    __shared__ float v1s[NN], v2s[NN];
    const int b = blockIdx.x >> 3;
    const int rg = blockIdx.x & 7;
    const int t = threadIdx.x;
    const int wid = t >> 5, lane = t & 31;

#pragma unroll
    for (int i = 0; i < 4; ++i) {
        v1s[t + i * 256] = g_v1[b * NN + t + i * 256];
        v2s[t + i * 256] = g_v2[b * NN + t + i * 256];
    }
    __syncthreads();

#pragma unroll 1
    for (int it = 0; it < 16; ++it) {
        const int ri = b * NN + rg * 128 + wid * 16 + it;
        uint32_t m = g_mask[(size_t)ri * 32 + lane];
        float s1 = 0.f, s2 = 0.f;
        while (m) {
            int bit = __ffs(m) - 1;
            m &= m - 1;
            s1 += v1s[lane * 32 + bit];
            s2 += v2s[lane * 32 + bit];
        }
#pragma unroll
        for (int o = 16; o > 0; o >>= 1) {
            s1 += __shfl_down_sync(0xffffffffu, s1, o);
            s2 += __shfl_down_sync(0xffffffffu, s2, o);
        }
        if (lane == 0) { g_s1[ri] = s1; g_s2[ri] = s2; }
    }
}

// ---------------------------------------------------------------------------
// GEMM fp16: nv[b, i0:+128, h0:+128] = adj[b] @ x, K=1024.
// A expanded from bitmask via 256-entry smem LUT (byte -> 8 packed fp16 0/1);
// B via cp.async double-buffer.
// ---------------------------------------------------------------------------
#define NKT 16
#define STAGE_B 32768          // A 16KB + B 16KB
#define LUT_OFF (2 * STAGE_B)  // 4KB LUT after the two stages
#define GEMM_SMEM (2 * STAGE_B + 4096)

__device__ __forceinline__ void expand_A(uint32_t sA, uint32_t lut,
                                         const uint32_t* mrow0, int kt) {
    const int t = threadIdx.x;
#pragma unroll
    for (int i = 0; i < 4; ++i) {
        const int idx = t + i * 256;         // 0..1023
        const int r = idx >> 3;              // row 0..127
        const int c = idx & 7;               // 16B chunk (8 halves)
        const uint32_t word = mrow0[r * 32 + 2 * kt + (c >> 2)];
        const uint32_t byte = (word >> ((c & 3) * 8)) & 0xffu;
        uint32_t a0, a1, a2, a3;
        asm volatile("ld.shared.v4.b32 {%0,%1,%2,%3}, [%4];"
                     : "=r"(a0), "=r"(a1), "=r"(a2), "=r"(a3)
                     : "r"(lut + byte * 16));
        const uint32_t soff = (uint32_t)(r * 128 + ((c ^ (r & 7)) * 16));
        asm volatile("st.shared.v4.b32 [%0], {%1,%2,%3,%4};"
                     :: "r"(sA + soff), "r"(a0), "r"(a1), "r"(a2), "r"(a3) : "memory");
    }
}

__device__ __forceinline__ void load_B(uint32_t sB, const __half* gB, int kt) {
    const int t = threadIdx.x;
    const int k0 = kt * 64;
#pragma unroll
    for (int i = 0; i < 4; ++i) {
        int idx = t + i * 256;
        int r = idx >> 3;
        int c = idx & 7;
        uint32_t soff = (uint32_t)(r * 128 + ((c ^ (r & 7)) * 16));
        cp_async16(sB + soff, gB + (size_t)r * NN + k0 + c * 8);
    }
    asm volatile("cp.async.commit_group;" ::: "memory");
}

__global__ void __launch_bounds__(256, 2) gemm_kernel(float* __restrict__ nv) {
    extern __shared__ __align__(1024) char dsm[];
    const uint32_t sbase = smem_u32(dsm);
    const uint32_t lut = sbase + LUT_OFF;
    const int tid = threadIdx.x;
    const int wid = tid >> 5, lane = tid & 31;
    const int warp_m = wid & 3, warp_n = wid >> 2;
    const int i0 = blockIdx.x * 128, h0 = blockIdx.y * 128;
    const int b = blockIdx.z;

    const uint32_t* mrow0 = g_mask + ((size_t)(b * NN + i0)) * 32;
    const __half* gB0 = g_xT + ((size_t)(b * HH + h0)) * NN;

    // build byte->fp16x8 LUT once
    {
        const uint32_t byte = (uint32_t)tid;   // 0..255
        uint4 u;
        u.x = ((byte >> 0) & 1u) * 0x3C00u | ((byte >> 1) & 1u) * 0x3C000000u;
        u.y = ((byte >> 2) & 1u) * 0x3C00u | ((byte >> 3) & 1u) * 0x3C000000u;
        u.z = ((byte >> 4) & 1u) * 0x3C00u | ((byte >> 5) & 1u) * 0x3C000000u;
        u.w = ((byte >> 6) & 1u) * 0x3C00u | ((byte >> 7) & 1u) * 0x3C000000u;
        asm volatile("st.shared.v4.b32 [%0], {%1,%2,%3,%4};"
                     :: "r"(lut + byte * 16), "r"(u.x), "r"(u.y), "r"(u.z), "r"(u.w) : "memory");
    }
    __syncthreads();

    float acc[2][8][4];
#pragma unroll
    for (int mi = 0; mi < 2; ++mi)
#pragma unroll
        for (int nf = 0; nf < 8; ++nf)
#pragma unroll
            for (int q = 0; q < 4; ++q) acc[mi][nf][q] = 0.f;

    const int rA = warp_m * 32 + (lane & 15);
    const int cselA = lane >> 4;
    const int rB0 = warp_n * 64 + (lane & 7) + ((lane >> 4) << 3);
    const int cselB = (lane >> 3) & 1;

    // prologue: stage 0
    expand_A(sbase, lut, mrow0, 0);
    load_B(sbase + 16384u, gB0, 0);

#pragma unroll 1
    for (int kt = 0; kt < NKT; ++kt) {
        if (kt + 1 < NKT) {
            const uint32_t snext = sbase + (uint32_t)((kt + 1) & 1) * STAGE_B;
            expand_A(snext, lut, mrow0, kt + 1);
            load_B(snext + 16384u, gB0, kt + 1);
            asm volatile("cp.async.wait_group 1;" ::: "memory");
        } else {
            asm volatile("cp.async.wait_group 0;" ::: "memory");
        }
        __syncthreads();

        const uint32_t sA = sbase + (uint32_t)(kt & 1) * STAGE_B;
        const uint32_t sB = sA + 16384u;
#pragma unroll
        for (int ks = 0; ks < 4; ++ks) {
            uint32_t a[2][4];
#pragma unroll
            for (int mi = 0; mi < 2; ++mi) {
                int row = rA + mi * 16;
                uint32_t ad = sA + (uint32_t)(row * 128 + (((ks * 2 + cselA) ^ (row & 7)) * 16));
                ldmx4(a[mi][0], a[mi][1], a[mi][2], a[mi][3], ad);
            }
            uint32_t bf[8][2];
#pragma unroll
            for (int nj = 0; nj < 4; ++nj) {
                int row = rB0 + nj * 16;
                uint32_t ad = sB + (uint32_t)(row * 128 + (((ks * 2 + cselB) ^ (row & 7)) * 16));
                uint32_t r0, r1, r2, r3;
                ldmx4(r0, r1, r2, r3, ad);
                bf[2 * nj][0] = r0; bf[2 * nj][1] = r1;
                bf[2 * nj + 1][0] = r2; bf[2 * nj + 1][1] = r3;
            }
#pragma unroll
            for (int mi = 0; mi < 2; ++mi)
#pragma unroll
                for (int nf = 0; nf < 8; ++nf)
                    mma16816(acc[mi][nf], a[mi], bf[nf]);
        }
        __syncthreads();
    }

    const int g = lane >> 2, t4 = lane & 3;
#pragma unroll
    for (int mi = 0; mi < 2; ++mi) {
#pragma unroll
        for (int nf = 0; nf < 8; ++nf) {
            int row0 = i0 + warp_m * 32 + mi * 16 + g;
            int col = h0 + warp_n * 64 + nf * 8 + t4 * 2;
            float* p0 = nv + ((size_t)(b * NN) + row0) * HH + col;
            *(float2*)p0 = make_float2(acc[mi][nf][0], acc[mi][nf][1]);
            *(float2*)(p0 + 8 * HH) = make_float2(acc[mi][nf][2], acc[mi][nf][3]);
        }
    }
}

// ---------------------------------------------------------------------------
// softmax: bitmask-driven, register-resident scores
// ---------------------------------------------------------------------------
__global__ void softmax_kernel(const float* __restrict__ nl, float* __restrict__ attn) {
    __shared__ float red[8];
    __shared__ float bc;
    const int row = blockIdx.x;
    const int b = row >> 10;
    const int tid = threadIdx.x;

    const float s1i = g_s1[row];
    const bool rv = nl[row] > 1e-6f;
    const uint32_t* mrow = g_mask + (size_t)row * 32;
    const float* nlb = nl + (size_t)b * NN;
    const float* s2b = g_s2 + (size_t)b * NN;

    float sc[4];
    float lmax = NEG_INF_F;
#pragma unroll
    for (int k = 0; k < 4; ++k) {
        const int j = tid + 256 * k;
        const uint32_t w = mrow[j >> 5];
        const bool v = (((w >> (j & 31)) & 1u) != 0u) && rv && (nlb[j] > 1e-6f);
        const float z = s1i + s2b[j];
        const float e = (z > 0.f) ? z : SLOPE_F * z;
        sc[k] = v ? e : NEG_INF_F;
        lmax = fmaxf(lmax, sc[k]);
    }
#pragma unroll
    for (int o = 16; o > 0; o >>= 1)
        lmax = fmaxf(lmax, __shfl_xor_sync(0xffffffffu, lmax, o));
    if ((tid & 31) == 0) red[tid >> 5] = lmax;
    __syncthreads();
    if (tid == 0) {
        float m = red[0];
#pragma unroll
        for (int k = 1; k < 8; ++k) m = fmaxf(m, red[k]);
        bc = m;
    }
    __syncthreads();
    const float m = bc;

    float lsum = 0.f;
#pragma unroll
    for (int k = 0; k < 4; ++k) {
        const float e = __expf(sc[k] - m);
        sc[k] = e;
        lsum += e;
    }
#pragma unroll
    for (int o = 16; o > 0; o >>= 1)
        lsum += __shfl_xor_sync(0xffffffffu, lsum, o);
    if ((tid & 31) == 0) red[tid >> 5] = lsum;
    __syncthreads();
    if (tid == 0) {
        float s = 0.f;
#pragma unroll
        for (int k = 0; k < 8; ++k) s += red[k];
        bc = 1.0f / s;
    }
    __syncthreads();
    const float inv = bc;

    float* orow = attn + (size_t)row * NN;
#pragma unroll
    for (int k = 0; k < 4; ++k)
        orow[tid + 256 * k] = sc[k] * inv;
}

// ---------------------------------------------------------------------------
// launch: three-stream overlap.
//   default: prep_mask -> [wait evX] gemm
//   s3:      prep_x (evX)
//   s2:      u -> v -> [wait evA: mask] s -> softmax (evB)
// ---------------------------------------------------------------------------
extern "C" void kernel_launch(void* const* d_in, const int* in_sizes, int n_in,
                              void* d_out, int out_size) {
    const float* x   = (const float*)d_in[0];   // (B, N, H)
    const float* nl  = (const float*)d_in[1];   // (B, N)
    const float* adj = (const float*)d_in[2];   // (B, N, N)
    const float* W   = (const float*)d_in[3];   // (H, H)
    const float* a   = (const float*)d_in[4];   // (2H, 1)

    float* nv   = (float*)d_out;
    float* attn = nv + (size_t)BB * NN * HH;

    static cudaStream_t s2 = nullptr, s3 = nullptr;
    static cudaEvent_t ev0 = nullptr, evA = nullptr, evB = nullptr, evX = nullptr;
    static int inited = 0;
    if (!inited) {
        cudaFuncSetAttribute(gemm_kernel, cudaFuncAttributeMaxDynamicSharedMemorySize, GEMM_SMEM);
        cudaStreamCreateWithFlags(&s2, cudaStreamNonBlocking);
        cudaStreamCreateWithFlags(&s3, cudaStreamNonBlocking);
        cudaEventCreateWithFlags(&ev0, cudaEventDisableTiming);
        cudaEventCreateWithFlags(&evA, cudaEventDisableTiming);
        cudaEventCreateWithFlags(&evB, cudaEventDisableTiming);
        cudaEventCreateWithFlags(&evX, cudaEventDisableTiming);
        inited = 1;
    }

    // fork side streams off the capture (default) stream
    cudaEventRecord(ev0, 0);
    cudaStreamWaitEvent(s2, ev0, 0);
    cudaStreamWaitEvent(s3, ev0, 0);

    // default: mask
    prep_mask_kernel<<<BB * NN, 256>>>(adj);
    cudaEventRecord(evA, 0);                    // mask ready

    // s3: xT
    prep_x_kernel<<<dim3(HH / 32, NN / 64, BB), 256, 0, s3>>>(x);
    cudaEventRecord(evX, s3);

    cudaStreamWaitEvent(0, evX, 0);
    gemm_kernel<<<dim3(NN / 128, HH / 128, BB), 256, GEMM_SMEM>>>(nv);

    // s2: chain B
    compute_u_kernel<<<96, 256, 0, s2>>>(W, a);
    compute_v_kernel<<<(BB * NN) / 8, 256, 0, s2>>>(x);
    cudaStreamWaitEvent(s2, evA, 0);            // need g_mask
    compute_s_kernel<<<BB * 8, 256, 0, s2>>>();
    softmax_kernel<<<BB * NN, 256, 0, s2>>>(nl, attn);
    cudaEventRecord(evB, s2);

    // join
    cudaStreamWaitEvent(0, evB, 0);
}

// round 14
// speedup vs baseline: 1.0587x; 1.0587x over previous
#include <cuda_runtime.h>
#include <cuda_fp16.h>
#include <cstdint>

#define BB 16
#define NN 1024
#define HH 768
#define NEG_INF_F (-9000000000000000.0f)
#define SLOPE_F 0.2f

// ---- static device scratch (no allocations allowed) ----
__device__ __align__(16) __half g_adjh[(size_t)BB * NN * NN];   // adj fp16 (exact 0/1) 33.5 MB
__device__ __align__(16) __half g_xT[(size_t)BB * HH * NN];     // xT fp16 [b][h][k] 25 MB
__device__ uint32_t g_mask[(size_t)BB * NN * 32];               // 2 MB
__device__ __align__(16) float g_u1[HH], g_u2[HH];
__device__ float g_v1[BB * NN], g_v2[BB * NN];
__device__ float g_s1[BB * NN], g_s2[BB * NN];

__device__ __forceinline__ uint32_t smem_u32(const void* p) {
    uint32_t a;
    asm("{ .reg .u64 t; cvta.to.shared.u64 t, %1; cvt.u32.u64 %0, t; }" : "=r"(a) : "l"(p));
    return a;
}
__device__ __forceinline__ void cp_async16(uint32_t dst, const void* src) {
    asm volatile("cp.async.cg.shared.global [%0], [%1], 16;" :: "r"(dst), "l"(src) : "memory");
}
__device__ __forceinline__ void ldmx4(uint32_t& r0, uint32_t& r1, uint32_t& r2, uint32_t& r3, uint32_t a) {
    asm volatile("ldmatrix.sync.aligned.m8n8.x4.shared.b16 {%0,%1,%2,%3}, [%4];"
                 : "=r"(r0), "=r"(r1), "=r"(r2), "=r"(r3) : "r"(a));
}
__device__ __forceinline__ void mma16816(float* d, const uint32_t* a, const uint32_t* b) {
    asm volatile("mma.sync.aligned.m16n8k16.row.col.f32.f16.f16.f32 "
                 "{%0,%1,%2,%3}, {%4,%5,%6,%7}, {%8,%9}, {%0,%1,%2,%3};"
                 : "+f"(d[0]), "+f"(d[1]), "+f"(d[2]), "+f"(d[3])
                 : "r"(a[0]), "r"(a[1]), "r"(a[2]), "r"(a[3]), "r"(b[0]), "r"(b[1]));
}

// ---------------------------------------------------------------------------
// prep_adj: fp32 -> fp16 (exact 0/1) + validity bitmask
// ---------------------------------------------------------------------------
__global__ void prep_adj_kernel(const float* __restrict__ adj) {
    __shared__ unsigned char s_nib[256];
    const int row = blockIdx.x;
    const int t = threadIdx.x;
    const float4 v = ((const float4*)(adj + (size_t)row * NN))[t];
    __half2 p0 = __floats2half2_rn(v.x, v.y);
    __half2 p1 = __floats2half2_rn(v.z, v.w);
    uint2 u;
    u.x = *(const uint32_t*)&p0;
    u.y = *(const uint32_t*)&p1;
    ((uint2*)(g_adjh + (size_t)row * NN))[t] = u;
    unsigned nib = (v.x > 1e-6f ? 1u : 0u) | (v.y > 1e-6f ? 2u : 0u) |
                   (v.z > 1e-6f ? 4u : 0u) | (v.w > 1e-6f ? 8u : 0u);
    s_nib[t] = (unsigned char)nib;
    __syncthreads();
    if (t < 32) {
        uint32_t w = 0;
#pragma unroll
        for (int i = 0; i < 8; ++i) w |= ((uint32_t)s_nib[t * 8 + i]) << (4 * i);
        g_mask[(size_t)row * 32 + t] = w;
    }
}

// ---------------------------------------------------------------------------
// prep_x: transpose to fp16 xT[b][h][k], packed half2 stores
// ---------------------------------------------------------------------------
__global__ void prep_x_kernel(const float* __restrict__ x) {
    __shared__ float tile[64][33];
    const int b = blockIdx.z;
    const int k0 = blockIdx.y * 64;
    const int h0 = blockIdx.x * 32;
    const int t = threadIdx.x;
    const int wid = t >> 5, lane = t & 31;

#pragma unroll
    for (int i = 0; i < 8; ++i) {
        int r = wid + i * 8;
        tile[r][lane] = x[((size_t)(b * NN + k0 + r)) * HH + h0 + lane];
    }
    __syncthreads();

    uint32_t* xo = (uint32_t*)g_xT;
#pragma unroll
    for (int i = 0; i < 4; ++i) {
        const int h = h0 + wid + i * 8;
        const __half2 p = __floats2half2_rn(tile[2 * lane][wid + i * 8],
                                            tile[2 * lane + 1][wid + i * 8]);
        const size_t base = ((size_t)(b * HH + h)) * (NN / 2) + (k0 >> 1);
        xo[base + lane] = *(const uint32_t*)&p;
    }
}

// ---------------------------------------------------------------------------
// u1 = W @ a[:H], u2 = W @ a[H:]  — one warp per output element
// ---------------------------------------------------------------------------
__global__ void compute_u_kernel(const float* __restrict__ W, const float* __restrict__ a) {
    const int g = blockIdx.x * 8 + (threadIdx.x >> 5);
    const int lane = threadIdx.x & 31;
    const float* wr = W + (size_t)g * HH;
    float u1 = 0.f, u2 = 0.f;
#pragma unroll
    for (int f = lane; f < HH; f += 32) {
        const float w = wr[f];
        u1 += w * a[f];
        u2 += w * a[HH + f];
    }
#pragma unroll
    for (int o = 16; o > 0; o >>= 1) {
        u1 += __shfl_down_sync(0xffffffffu, u1, o);
        u2 += __shfl_down_sync(0xffffffffu, u2, o);
    }
    if (lane == 0) { g_u1[g] = u1; g_u2[g] = u2; }
}

// ---------------------------------------------------------------------------
// v1[b,j] = x[b,j,:].u1 ; v2 = x.u2   (one warp per row, exact fp32)
// ---------------------------------------------------------------------------
__global__ void compute_v_kernel(const float* __restrict__ x) {
    const int row = blockIdx.x * 8 + (threadIdx.x >> 5);
    const int lane = threadIdx.x & 31;
    const float4* r = (const float4*)(x + (size_t)row * HH);
    const float4* u1 = (const float4*)g_u1;
    const float4* u2 = (const float4*)g_u2;
    float d1 = 0.f, d2 = 0.f;
#pragma unroll
    for (int k = lane; k < HH / 4; k += 32) {
        float4 v = r[k], w1 = u1[k], w2 = u2[k];
        d1 += v.x * w1.x + v.y * w1.y + v.z * w1.z + v.w * w1.w;
        d2 += v.x * w2.x + v.y * w2.y + v.z * w2.z + v.w * w2.w;
    }
#pragma unroll
    for (int o = 16; o > 0; o >>= 1) {
        d1 += __shfl_down_sync(0xffffffffu, d1, o);
        d2 += __shfl_down_sync(0xffffffffu, d2, o);
    }
    if (lane == 0) { g_v1[row] = d1; g_v2[row] = d2; }
}

// ---------------------------------------------------------------------------
// s1[b,i] = sum_{j in mask(i)} v1[b,j]   (exact fp32)
// ---------------------------------------------------------------------------
__global__ void compute_s_kernel() {
    __shared__ float v1s[NN], v2s[NN];
    const int b = blockIdx.x >> 3;
    const int rg = blockIdx.x & 7;
    const int t = threadIdx.x;
    const int wid = t >> 5, lane = t & 31;

#pragma unroll
    for (int i = 0; i < 4; ++i) {
        v1s[t + i * 256] = g_v1[b * NN + t + i * 256];
        v2s[t + i * 256] = g_v2[b * NN + t + i * 256];
    }
    __syncthreads();

#pragma unroll 1
    for (int it = 0; it < 16; ++it) {
        const int ri = b * NN + rg * 128 + wid * 16 + it;
        uint32_t m = g_mask[(size_t)ri * 32 + lane];
        float s1 = 0.f, s2 = 0.f;
        while (m) {
            int bit = __ffs(m) - 1;
            m &= m - 1;
            s1 += v1s[lane * 32 + bit];
            s2 += v2s[lane * 32 + bit];
        }
#pragma unroll
        for (int o = 16; o > 0; o >>= 1) {
            s1 += __shfl_down_sync(0xffffffffu, s1, o);
            s2 += __shfl_down_sync(0xffffffffu, s2, o);
        }
        if (lane == 0) { g_s1[ri] = s1; g_s2[ri] = s2; }
    }
}

// ---------------------------------------------------------------------------
// GEMM fp16 single-pass: nv[b, i0:+128, h0:+128] = adj[b] @ x, K=1024
// (round-11 verified version: A and B both via cp.async double-buffer)
// ---------------------------------------------------------------------------
#define NKT 16
#define STAGE_B 32768          // A 16KB + B 16KB
#define GEMM_SMEM (2 * STAGE_B)

__device__ __forceinline__ void gemm_load(uint32_t sbase, int stage,
                                          const __half* gA, const __half* gB, int kt) {
    const int t = threadIdx.x;
    const uint32_t sA = sbase + (uint32_t)stage * STAGE_B;
    const uint32_t sB = sA + 16384u;
    const int k0 = kt * 64;
#pragma unroll
    for (int i = 0; i < 4; ++i) {
        int idx = t + i * 256;           // 0..1023
        int r = idx >> 3;                // row 0..127
        int c = idx & 7;                 // 16B chunk
        uint32_t soff = (uint32_t)(r * 128 + ((c ^ (r & 7)) * 16));
        cp_async16(sA + soff, gA + (size_t)r * NN + k0 + c * 8);
        cp_async16(sB + soff, gB + (size_t)r * NN + k0 + c * 8);
    }
    asm volatile("cp.async.commit_group;" ::: "memory");
}

__global__ void __launch_bounds__(256, 2) gemm_kernel(float* __restrict__ nv) {
    extern __shared__ __align__(1024) char dsm[];
    const uint32_t sbase = smem_u32(dsm);
    const int tid = threadIdx.x;
    const int wid = tid >> 5, lane = tid & 31;
    const int warp_m = wid & 3, warp_n = wid >> 2;
    const int i0 = blockIdx.x * 128, h0 = blockIdx.y * 128;
    const int b = blockIdx.z;

    const __half* gA0 = g_adjh + ((size_t)(b * NN + i0)) * NN;
    const __half* gB0 = g_xT + ((size_t)(b * HH + h0)) * NN;

    float acc[2][8][4];
#pragma unroll
    for (int mi = 0; mi < 2; ++mi)
#pragma unroll
        for (int nf = 0; nf < 8; ++nf)
#pragma unroll
            for (int q = 0; q < 4; ++q) acc[mi][nf][q] = 0.f;

    const int rA = warp_m * 32 + (lane & 15);
    const int cselA = lane >> 4;
    const int rB0 = warp_n * 64 + (lane & 7) + ((lane >> 4) << 3);
    const int cselB = (lane >> 3) & 1;

    gemm_load(sbase, 0, gA0, gB0, 0);

#pragma unroll 1
    for (int kt = 0; kt < NKT; ++kt) {
        if (kt + 1 < NKT) {
            gemm_load(sbase, (kt + 1) & 1, gA0, gB0, kt + 1);
            asm volatile("cp.async.wait_group 1;" ::: "memory");
        } else {
            asm volatile("cp.async.wait_group 0;" ::: "memory");
        }
        __syncthreads();

        const uint32_t sA = sbase + (uint32_t)(kt & 1) * STAGE_B;
        const uint32_t sB = sA + 16384u;
#pragma unroll
        for (int ks = 0; ks < 4; ++ks) {
            uint32_t a[2][4];
#pragma unroll
            for (int mi = 0; mi < 2; ++mi) {
                int row = rA + mi * 16;
                uint32_t ad = sA + (uint32_t)(row * 128 + (((ks * 2 + cselA) ^ (row & 7)) * 16));
                ldmx4(a[mi][0], a[mi][1], a[mi][2], a[mi][3], ad);
            }
            uint32_t bf[8][2];
#pragma unroll
            for (int nj = 0; nj < 4; ++nj) {
                int row = rB0 + nj * 16;
                uint32_t ad = sB + (uint32_t)(row * 128 + (((ks * 2 + cselB) ^ (row & 7)) * 16));
                uint32_t r0, r1, r2, r3;
                ldmx4(r0, r1, r2, r3, ad);
                bf[2 * nj][0] = r0; bf[2 * nj][1] = r1;
                bf[2 * nj + 1][0] = r2; bf[2 * nj + 1][1] = r3;
            }
#pragma unroll
            for (int mi = 0; mi < 2; ++mi)
#pragma unroll
                for (int nf = 0; nf < 8; ++nf)
                    mma16816(acc[mi][nf], a[mi], bf[nf]);
        }
        __syncthreads();
    }

    const int g = lane >> 2, t4 = lane & 3;
#pragma unroll
    for (int mi = 0; mi < 2; ++mi) {
#pragma unroll
        for (int nf = 0; nf < 8; ++nf) {
            int row0 = i0 + warp_m * 32 + mi * 16 + g;
            int col = h0 + warp_n * 64 + nf * 8 + t4 * 2;
            float* p0 = nv + ((size_t)(b * NN) + row0) * HH + col;
            *(float2*)p0 = make_float2(acc[mi][nf][0], acc[mi][nf][1]);
            *(float2*)(p0 + 8 * HH) = make_float2(acc[mi][nf][2], acc[mi][nf][3]);
        }
    }
}

// ---------------------------------------------------------------------------
// softmax: bitmask-driven, register-resident scores
// ---------------------------------------------------------------------------
__global__ void softmax_kernel(const float* __restrict__ nl, float* __restrict__ attn) {
    __shared__ float red[8];
    __shared__ float bc;
    const int row = blockIdx.x;
    const int b = row >> 10;
    const int tid = threadIdx.x;

    const float s1i = g_s1[row];
    const bool rv = nl[row] > 1e-6f;
    const uint32_t* mrow = g_mask + (size_t)row * 32;
    const float* nlb = nl + (size_t)b * NN;
    const float* s2b = g_s2 + (size_t)b * NN;

    float sc[4];
    float lmax = NEG_INF_F;
#pragma unroll
    for (int k = 0; k < 4; ++k) {
        const int j = tid + 256 * k;
        const uint32_t w = mrow[j >> 5];
        const bool v = (((w >> (j & 31)) & 1u) != 0u) && rv && (nlb[j] > 1e-6f);
        const float z = s1i + s2b[j];
        const float e = (z > 0.f) ? z : SLOPE_F * z;
        sc[k] = v ? e : NEG_INF_F;
        lmax = fmaxf(lmax, sc[k]);
    }
#pragma unroll
    for (int o = 16; o > 0; o >>= 1)
        lmax = fmaxf(lmax, __shfl_xor_sync(0xffffffffu, lmax, o));
    if ((tid & 31) == 0) red[tid >> 5] = lmax;
    __syncthreads();
    if (tid == 0) {
        float m = red[0];
#pragma unroll
        for (int k = 1; k < 8; ++k) m = fmaxf(m, red[k]);
        bc = m;
    }
    __syncthreads();
    const float m = bc;

    float lsum = 0.f;
#pragma unroll
    for (int k = 0; k < 4; ++k) {
        const float e = __expf(sc[k] - m);
        sc[k] = e;
        lsum += e;
    }
#pragma unroll
    for (int o = 16; o > 0; o >>= 1)
        lsum += __shfl_xor_sync(0xffffffffu, lsum, o);
    if ((tid & 31) == 0) red[tid >> 5] = lsum;
    __syncthreads();
    if (tid == 0) {
        float s = 0.f;
#pragma unroll
        for (int k = 0; k < 8; ++k) s += red[k];
        bc = 1.0f / s;
    }
    __syncthreads();
    const float inv = bc;

    float* orow = attn + (size_t)row * NN;
#pragma unroll
    for (int k = 0; k < 4; ++k)
        orow[tid + 256 * k] = sc[k] * inv;
}

// ---------------------------------------------------------------------------
// launch: concurrent preps + overlapped chain B.
//   default: prep_adj (evA) -> [wait evX] gemm
//   s3:      prep_x (evX)
//   s2:      u -> v -> [wait evA] s -> softmax (evB)
// ---------------------------------------------------------------------------
extern "C" void kernel_launch(void* const* d_in, const int* in_sizes, int n_in,
                              void* d_out, int out_size) {
    const float* x   = (const float*)d_in[0];   // (B, N, H)
    const float* nl  = (const float*)d_in[1];   // (B, N)
    const float* adj = (const float*)d_in[2];   // (B, N, N)
    const float* W   = (const float*)d_in[3];   // (H, H)
    const float* a   = (const float*)d_in[4];   // (2H, 1)

    float* nv   = (float*)d_out;
    float* attn = nv + (size_t)BB * NN * HH;

    static cudaStream_t s2 = nullptr, s3 = nullptr;
    static cudaEvent_t ev0 = nullptr, evA = nullptr, evB = nullptr, evX = nullptr;
    static int inited = 0;
    if (!inited) {
        cudaFuncSetAttribute(gemm_kernel, cudaFuncAttributeMaxDynamicSharedMemorySize, GEMM_SMEM);
        cudaStreamCreateWithFlags(&s2, cudaStreamNonBlocking);
        cudaStreamCreateWithFlags(&s3, cudaStreamNonBlocking);
        cudaEventCreateWithFlags(&ev0, cudaEventDisableTiming);
        cudaEventCreateWithFlags(&evA, cudaEventDisableTiming);
        cudaEventCreateWithFlags(&evB, cudaEventDisableTiming);
        cudaEventCreateWithFlags(&evX, cudaEventDisableTiming);
        inited = 1;
    }

    // fork side streams off the capture (default) stream
    cudaEventRecord(ev0, 0);
    cudaStreamWaitEvent(s2, ev0, 0);
    cudaStreamWaitEvent(s3, ev0, 0);

    // default: adj -> fp16 + mask
    prep_adj_kernel<<<BB * NN, 256>>>(adj);
    cudaEventRecord(evA, 0);                    // adjh + mask ready

    // s3: xT (concurrent with prep_adj)
    prep_x_kernel<<<dim3(HH / 32, NN / 64, BB), 256, 0, s3>>>(x);
    cudaEventRecord(evX, s3);

    cudaStreamWaitEvent(0, evX, 0);
    gemm_kernel<<<dim3(NN / 128, HH / 128, BB), 256, GEMM_SMEM>>>(nv);

    // s2: chain B
    compute_u_kernel<<<96, 256, 0, s2>>>(W, a);
    compute_v_kernel<<<(BB * NN) / 8, 256, 0, s2>>>(x);
    cudaStreamWaitEvent(s2, evA, 0);            // need g_mask
    compute_s_kernel<<<BB * 8, 256, 0, s2>>>();
    softmax_kernel<<<BB * NN, 256, 0, s2>>>(nl, attn);
    cudaEventRecord(evB, s2);

    // join
    cudaStreamWaitEvent(0, evB, 0);
}